// round 12
// baseline (speedup 1.0000x reference)
#include <cuda_runtime.h>
#include <cuda_bf16.h>
#include <cstdint>

// ---------------------------------------------------------------------------
// Problem constants
// ---------------------------------------------------------------------------
#define NPF 20000
#define NGW 100000
#define NSW 30000
#define D   128

#define EPG 1600000
#define EGP 640000
#define EPS 480000
#define ESP 320000
#define ETOT (EPG + EGP + EPS + ESP)

#define NTOT (NGW + NPF + NSW + NPF)

// ---------------------------------------------------------------------------
// Device scratch (no allocations allowed -> __device__ globals)
// ---------------------------------------------------------------------------
__device__ float g_mean_gw[(size_t)NGW * D];
__device__ float g_mean_sw[(size_t)NSW * D];
__device__ float g_mean_gp[(size_t)NPF * D];
__device__ float g_mean_sp[(size_t)NPF * D];
__device__ int   g_cnt[NTOT];
__device__ int   g_rowptr[NTOT];
__device__ int   g_cursor[NTOT];
__device__ int   g_perm[ETOT];
__device__ int   g_partials[4 * 128];
__device__ float g_wr_comb[D * D];

// ---------------------------------------------------------------------------
// small utility kernels
// ---------------------------------------------------------------------------
__global__ void zero_int_kernel(int* __restrict__ p, int n4) {
    int i = blockIdx.x * blockDim.x + threadIdx.x;
    if (i < n4) reinterpret_cast<int4*>(p)[i] = make_int4(0, 0, 0, 0);
}

__global__ void addw_kernel(const float* __restrict__ a, const float* __restrict__ b,
                            float* __restrict__ o) {
    int i = blockIdx.x * blockDim.x + threadIdx.x;
    if (i < D * D) o[i] = a[i] + b[i];
}

// ---------------------------------------------------------------------------
// Fused CSR build (proven R5 kernels): one histogram / permute over all 4
// relations; per-relation scans with grid.y = relation.
// ---------------------------------------------------------------------------
__global__ void hist_f(const int* __restrict__ pgd, const int* __restrict__ gpd,
                       const int* __restrict__ psd, const int* __restrict__ spd,
                       int* __restrict__ cnt) {
    int e = blockIdx.x * blockDim.x + threadIdx.x;
    if (e < EPG)                        atomicAdd(&cnt[pgd[e]], 1);
    else if (e < EPG + EGP)             atomicAdd(&cnt[NGW + gpd[e - EPG]], 1);
    else if (e < EPG + EGP + EPS)       atomicAdd(&cnt[NGW + NPF + psd[e - EPG - EGP]], 1);
    else if (e < ETOT)                  atomicAdd(&cnt[NGW + NPF + NSW + spd[e - EPG - EGP - EPS]], 1);
}

__global__ void scan_reduce_f(const int* __restrict__ cnt, int* __restrict__ partials) {
    const int nbs[4]  = {98, 20, 30, 20};
    const int offs[4] = {0, NGW, NGW + NPF, NGW + NPF + NSW};
    const int ns[4]   = {NGW, NPF, NSW, NPF};
    int r = blockIdx.y;
    if ((int)blockIdx.x >= nbs[r]) return;
    const int* c = cnt + offs[r];
    int n = ns[r];
    __shared__ int s[256];
    int t = threadIdx.x;
    int base = blockIdx.x * 1024 + t * 4;
    int sum = 0;
#pragma unroll
    for (int j = 0; j < 4; j++) {
        int idx = base + j;
        if (idx < n) sum += c[idx];
    }
    s[t] = sum;
    __syncthreads();
    for (int off = 128; off > 0; off >>= 1) {
        if (t < off) s[t] += s[t + off];
        __syncthreads();
    }
    if (t == 0) partials[r * 128 + blockIdx.x] = s[0];
}

// parallel exclusive scan of partials for all 4 relations (1 block)
__global__ void scan_partials_all(int* __restrict__ partials) {
    __shared__ int s[128];
    int t = threadIdx.x;
    for (int r = 0; r < 4; r++) {
        int v = partials[r * 128 + t];
        s[t] = v;
        __syncthreads();
        for (int off = 1; off < 128; off <<= 1) {
            int y = (t >= off) ? s[t - off] : 0;
            __syncthreads();
            s[t] += y;
            __syncthreads();
        }
        partials[r * 128 + t] = s[t] - v;
        __syncthreads();
    }
}

__global__ void scan_write_f(const int* __restrict__ cnt,
                             const int* __restrict__ partials,
                             int* __restrict__ rowptr,
                             int* __restrict__ cursor) {
    const int nbs[4]  = {98, 20, 30, 20};
    const int offs[4] = {0, NGW, NGW + NPF, NGW + NPF + NSW};
    const int ns[4]   = {NGW, NPF, NSW, NPF};
    int r = blockIdx.y;
    if ((int)blockIdx.x >= nbs[r]) return;
    const int* c = cnt + offs[r];
    int* rp = rowptr + offs[r];
    int* cu = cursor + offs[r];
    int n = ns[r];

    __shared__ int wsum[8];
    __shared__ int woff[8];
    int t = threadIdx.x;
    int lane = t & 31, warp = t >> 5;
    int base = blockIdx.x * 1024 + t * 4;
    int v[4];
    int tsum = 0;
#pragma unroll
    for (int j = 0; j < 4; j++) {
        int idx = base + j;
        v[j] = (idx < n) ? c[idx] : 0;
        tsum += v[j];
    }
    int incl = tsum;
#pragma unroll
    for (int o = 1; o < 32; o <<= 1) {
        int y = __shfl_up_sync(0xffffffffu, incl, o);
        if (lane >= o) incl += y;
    }
    int excl = incl - tsum;
    if (lane == 31) wsum[warp] = incl;
    __syncthreads();
    if (t == 0) {
        int rr = 0;
        for (int i = 0; i < 8; i++) { woff[i] = rr; rr += wsum[i]; }
    }
    __syncthreads();
    int run = partials[r * 128 + blockIdx.x] + woff[warp] + excl;
#pragma unroll
    for (int j = 0; j < 4; j++) {
        int idx = base + j;
        if (idx < n) { rp[idx] = run; cu[idx] = run; run += v[j]; }
    }
}

__global__ void permute_f(const int* __restrict__ pgs, const int* __restrict__ pgd,
                          const int* __restrict__ gps, const int* __restrict__ gpd,
                          const int* __restrict__ pss, const int* __restrict__ psd,
                          const int* __restrict__ sps, const int* __restrict__ spd,
                          int* __restrict__ cursor, int* __restrict__ perm) {
    int e = blockIdx.x * blockDim.x + threadIdx.x;
    const int *src, *dst;
    int off, poff, le;
    if (e < EPG)                  { src = pgs; dst = pgd; off = 0;               poff = 0;               le = e; }
    else if (e < EPG + EGP)       { src = gps; dst = gpd; off = NGW;             poff = EPG;             le = e - EPG; }
    else if (e < EPG + EGP + EPS) { src = pss; dst = psd; off = NGW + NPF;       poff = EPG + EGP;       le = e - EPG - EGP; }
    else if (e < ETOT)            { src = sps; dst = spd; off = NGW + NPF + NSW; poff = EPG + EGP + EPS; le = e - EPG - EGP - EPS; }
    else return;
    int pos = atomicAdd(&cursor[off + dst[le]], 1);
    perm[poff + pos] = src[le];
}

// ---------------------------------------------------------------------------
// Job descriptors for the heterogeneous mega kernel
// ---------------------------------------------------------------------------
struct GemmJob {
    const float *A0, *A1, *A2;
    const float *W0, *W1, *W2;
    const float *bias1, *bias2, *whead, *bhead;
    float* out;
    int row_base, n_rows, nseg, mode, nblocks;
};
struct AggJob {
    const float* x;
    const int* rowptr;
    const int* perm;
    float* outmean;
    int n0, n1, N, E, nblocks;
};

// ---------------------------------------------------------------------------
// agg path: one warp per destination node, 8-edge load batching (high MLP —
// needed because mega-kernel register allocation caps occupancy).
// ---------------------------------------------------------------------------
__device__ __forceinline__ void agg_path(const AggJob& jb, int rblk, int t) {
    int w = jb.n0 + rblk * 8 + (t >> 5);
    int lane = t & 31;
    if (w >= jb.n1) return;

    int start = jb.rowptr[w];
    int end   = (w + 1 < jb.N) ? jb.rowptr[w + 1] : jb.E;
    const float* x = jb.x;

    float4 acc = make_float4(0.f, 0.f, 0.f, 0.f);
    for (int e0 = start; e0 < end; e0 += 32) {
        int idx = (e0 + lane < end) ? jb.perm[e0 + lane] : 0;
        int m = min(32, end - e0);
        int j = 0;
        for (; j + 8 <= m; j += 8) {
            float4 v[8];
#pragma unroll
            for (int q = 0; q < 8; q++) {
                int s = __shfl_sync(0xffffffffu, idx, j + q);
                v[q] = *reinterpret_cast<const float4*>(x + (size_t)s * D + lane * 4);
            }
#pragma unroll
            for (int q = 0; q < 8; q++) {
                acc.x += v[q].x; acc.y += v[q].y; acc.z += v[q].z; acc.w += v[q].w;
            }
        }
        for (; j < m; j++) {
            int s = __shfl_sync(0xffffffffu, idx, j);
            float4 v = *reinterpret_cast<const float4*>(x + (size_t)s * D + lane * 4);
            acc.x += v.x; acc.y += v.y; acc.z += v.z; acc.w += v.w;
        }
    }
    float inv = 1.0f / fmaxf((float)(end - start), 1.0f);
    acc.x *= inv; acc.y *= inv; acc.z *= inv; acc.w *= inv;
    *reinterpret_cast<float4*>(jb.outmean + (size_t)w * D + lane * 4) = acc;
}

// ---------------------------------------------------------------------------
// gemm path: proven f32x2 128x128-tile GEMM, runtime nseg/mode.
// ---------------------------------------------------------------------------
__device__ __forceinline__ void gemm_path(const GemmJob& g, int bid, int t,
                                          float (*As)[132], float (*Ws)[132],
                                          float* red)
{
    const int row0 = g.row_base + bid * 128;
    const int trow = t >> 4;
    const int tcol = t & 15;

    const float* Aseg[3] = {g.A0, g.A1, g.A2};
    const float* Wseg[3] = {g.W0, g.W1, g.W2};

    unsigned long long accp[8][4];
#pragma unroll
    for (int i = 0; i < 8; i++)
#pragma unroll
        for (int j2 = 0; j2 < 4; j2++) accp[i][j2] = 0ull;

    const int nchunks = g.nseg * 8;
    for (int ch = 0; ch < nchunks; ch++) {
        const int seg  = ch >> 3;
        const int kin0 = (ch & 7) * 16;
        const float* A = Aseg[seg];
        const float* W = Wseg[seg];

#pragma unroll
        for (int it = 0; it < 2; it++) {
            int idx  = t + it * 256;
            int row  = idx >> 2;
            int q    = idx & 3;
            int grow = row0 + row;
            float4 v = make_float4(0.f, 0.f, 0.f, 0.f);
            if (grow < g.n_rows)
                v = *reinterpret_cast<const float4*>(A + (size_t)grow * D + kin0 + q * 4);
            As[q * 4 + 0][row] = v.x;
            As[q * 4 + 1][row] = v.y;
            As[q * 4 + 2][row] = v.z;
            As[q * 4 + 3][row] = v.w;
        }
#pragma unroll
        for (int it = 0; it < 2; it++) {
            int idx = t + it * 256;
            int kk  = idx >> 5;
            int cq  = idx & 31;
            float4 w = *reinterpret_cast<const float4*>(W + (size_t)(kin0 + kk) * D + cq * 4);
            *reinterpret_cast<float4*>(&Ws[kk][cq * 4]) = w;
        }
        __syncthreads();

#pragma unroll
        for (int kk = 0; kk < 16; kk++) {
            float4 a0 = *reinterpret_cast<const float4*>(&As[kk][trow * 4]);
            float4 a1 = *reinterpret_cast<const float4*>(&As[kk][64 + trow * 4]);
            unsigned long long wp[4];
            wp[0] = *reinterpret_cast<const unsigned long long*>(&Ws[kk][tcol * 4]);
            wp[1] = *reinterpret_cast<const unsigned long long*>(&Ws[kk][tcol * 4 + 2]);
            wp[2] = *reinterpret_cast<const unsigned long long*>(&Ws[kk][64 + tcol * 4]);
            wp[3] = *reinterpret_cast<const unsigned long long*>(&Ws[kk][64 + tcol * 4 + 2]);
            float a[8] = {a0.x, a0.y, a0.z, a0.w, a1.x, a1.y, a1.z, a1.w};
#pragma unroll
            for (int i = 0; i < 8; i++) {
                unsigned long long ap;
                asm("mov.b64 %0, {%1, %1};" : "=l"(ap) : "f"(a[i]));
#pragma unroll
                for (int j2 = 0; j2 < 4; j2++)
                    asm("fma.rn.f32x2 %0, %1, %2, %0;"
                        : "+l"(accp[i][j2]) : "l"(ap), "l"(wp[j2]));
            }
        }
        __syncthreads();
    }

    float acc[8][8];
#pragma unroll
    for (int i = 0; i < 8; i++)
#pragma unroll
        for (int j2 = 0; j2 < 4; j2++)
            asm("mov.b64 {%0, %1}, %2;"
                : "=f"(acc[i][2 * j2]), "=f"(acc[i][2 * j2 + 1]) : "l"(accp[i][j2]));

    int cidx[8], ridx[8];
#pragma unroll
    for (int j = 0; j < 8; j++)
        cidx[j] = (j < 4) ? (tcol * 4 + j) : (64 + tcol * 4 + (j - 4));
#pragma unroll
    for (int i = 0; i < 8; i++)
        ridx[i] = (i < 4) ? (trow * 4 + i) : (64 + trow * 4 + (i - 4));

    float b[8];
#pragma unroll
    for (int j = 0; j < 8; j++)
        b[j] = g.bias1[cidx[j]] + (g.bias2 ? g.bias2[cidx[j]] : 0.f);

    if (g.mode == 0) {
#pragma unroll
        for (int i = 0; i < 8; i++) {
            int grow = row0 + ridx[i];
            if (grow < g.n_rows) {
#pragma unroll
                for (int j = 0; j < 8; j++)
                    g.out[(size_t)grow * D + cidx[j]] = fmaxf(acc[i][j] + b[j], 0.f);
            }
        }
    } else {
        float wh[8];
#pragma unroll
        for (int j = 0; j < 8; j++) wh[j] = g.whead[cidx[j]];
        if (t < 128) red[t] = 0.f;
        __syncthreads();
#pragma unroll
        for (int i = 0; i < 8; i++) {
            float partial = 0.f;
#pragma unroll
            for (int j = 0; j < 8; j++)
                partial += fmaxf(acc[i][j] + b[j], 0.f) * wh[j];
            atomicAdd(&red[ridx[i]], partial);
        }
        __syncthreads();
        if (t < 128) {
            int grow = row0 + t;
            if (grow < g.n_rows) g.out[grow] = red[t] + g.bhead[0];
        }
    }
}

// ---------------------------------------------------------------------------
// mega kernel: heterogeneous block dispatch (up to 2 gemm jobs + 3 agg jobs).
// Gemm blocks come first so the opening waves carry FMA work while agg
// blocks keep the LSU/LTS busy -> pipe-level overlap within one launch.
// ---------------------------------------------------------------------------
__global__ __launch_bounds__(256) void mega_kernel(
    GemmJob g0, GemmJob g1, AggJob a0, AggJob a1, AggJob a2)
{
    __shared__ float As[16][132];
    __shared__ float Ws[16][132];
    __shared__ float red[128];

    int bid = blockIdx.x;
    int t = threadIdx.x;

    if (bid < g0.nblocks) { gemm_path(g0, bid, t, As, Ws, red); return; }
    bid -= g0.nblocks;
    if (bid < g1.nblocks) { gemm_path(g1, bid, t, As, Ws, red); return; }
    bid -= g1.nblocks;
    if (bid < a0.nblocks) { agg_path(a0, bid, t); return; }
    bid -= a0.nblocks;
    if (bid < a1.nblocks) { agg_path(a1, bid, t); return; }
    bid -= a1.nblocks;
    if (bid < a2.nblocks) { agg_path(a2, bid, t); }
}

// ---------------------------------------------------------------------------
// Launch: single stream; overlap is structural (within launches).
// ---------------------------------------------------------------------------
extern "C" void kernel_launch(void* const* d_in, const int* in_sizes, int n_in,
                              void* d_out, int out_size)
{
    const float* x_pfas = (const float*)d_in[0];
    const float* x_gw   = (const float*)d_in[1];
    const float* x_sw   = (const float*)d_in[2];
    const int* ei_pg_src = (const int*)d_in[3];
    const int* ei_pg_dst = (const int*)d_in[4];
    const int* ei_gp_src = (const int*)d_in[5];
    const int* ei_gp_dst = (const int*)d_in[6];
    const int* ei_ps_src = (const int*)d_in[7];
    const int* ei_ps_dst = (const int*)d_in[8];
    const int* ei_sp_src = (const int*)d_in[9];
    const int* ei_sp_dst = (const int*)d_in[10];
    const float* Wl_pg = (const float*)d_in[11];
    const float* bl_pg = (const float*)d_in[12];
    const float* Wr_pg = (const float*)d_in[13];
    const float* Wl_gp = (const float*)d_in[14];
    const float* bl_gp = (const float*)d_in[15];
    const float* Wr_gp = (const float*)d_in[16];
    const float* Wl_ps = (const float*)d_in[17];
    const float* bl_ps = (const float*)d_in[18];
    const float* Wr_ps = (const float*)d_in[19];
    const float* Wl_sp = (const float*)d_in[20];
    const float* bl_sp = (const float*)d_in[21];
    const float* Wr_sp = (const float*)d_in[22];
    const float* W_gw  = (const float*)d_in[23];
    const float* b_gw  = (const float*)d_in[24];
    const float* W_sw  = (const float*)d_in[25];
    const float* b_sw  = (const float*)d_in[26];

    float* out = (float*)d_out;
    float* out_hpf = out;                       // [20000, 128]
    float* out_gw  = out + (size_t)NPF * D;     // [100000]
    float* out_sw  = out_gw + NGW;              // [30000]

    static float *mean_gw = nullptr, *mean_sw = nullptr, *mean_gp = nullptr, *mean_sp = nullptr;
    static float *wr_comb = nullptr;
    static int *cnt = nullptr, *rowptr = nullptr, *cursor = nullptr, *perm = nullptr, *partials = nullptr;
    if (!mean_gw) {
        cudaGetSymbolAddress((void**)&mean_gw, g_mean_gw);
        cudaGetSymbolAddress((void**)&mean_sw, g_mean_sw);
        cudaGetSymbolAddress((void**)&mean_gp, g_mean_gp);
        cudaGetSymbolAddress((void**)&mean_sp, g_mean_sp);
        cudaGetSymbolAddress((void**)&wr_comb, g_wr_comb);
        cudaGetSymbolAddress((void**)&cnt, g_cnt);
        cudaGetSymbolAddress((void**)&rowptr, g_rowptr);
        cudaGetSymbolAddress((void**)&cursor, g_cursor);
        cudaGetSymbolAddress((void**)&perm, g_perm);
        cudaGetSymbolAddress((void**)&partials, g_partials);
    }

    const int off_pg = 0;
    const int off_gp = NGW;
    const int off_ps = NGW + NPF;
    const int off_sp = NGW + NPF + NSW;
    const int poff_pg = 0;
    const int poff_gp = EPG;
    const int poff_ps = EPG + EGP;
    const int poff_sp = EPG + EGP + EPS;

    // ---- 1) zero counters + fold Wr weights ----
    zero_int_kernel<<<(NTOT / 4 + 255) / 256, 256>>>(cnt, NTOT / 4);
    addw_kernel<<<(D * D + 255) / 256, 256>>>(Wr_gp, Wr_sp, wr_comb);

    // ---- 2) fused CSR build ----
    hist_f<<<(ETOT + 255) / 256, 256>>>(ei_pg_dst, ei_gp_dst, ei_ps_dst, ei_sp_dst, cnt);
    {
        dim3 g(98, 4);
        scan_reduce_f<<<g, 256>>>(cnt, partials);
        scan_partials_all<<<1, 128>>>(partials);
        scan_write_f<<<g, 256>>>(cnt, partials, rowptr, cursor);
    }
    permute_f<<<(ETOT + 255) / 256, 256>>>(
        ei_pg_src, ei_pg_dst, ei_gp_src, ei_gp_dst,
        ei_ps_src, ei_ps_dst, ei_sp_src, ei_sp_dst,
        cursor, perm);

    // ---- 3) heterogeneous phases ----
    GemmJob GZ = {};   // nblocks = 0
    AggJob  AZ = {};

    auto mkAgg = [&](const float* x, int off, int poff, int N, int E,
                     float* mean, int n0, int n1) {
        AggJob j;
        j.x = x; j.rowptr = rowptr + off; j.perm = perm + poff;
        j.outmean = mean; j.n0 = n0; j.n1 = n1; j.N = N; j.E = E;
        j.nblocks = (n1 - n0 + 7) / 8;
        return j;
    };

    // gw slices
    const int gb[5] = {0, 25600, 51200, 76800, NGW};

    AggJob aGP  = mkAgg(x_gw, off_gp, poff_gp, NPF, EGP, mean_gp, 0, NPF);
    AggJob aSP  = mkAgg(x_sw, off_sp, poff_sp, NPF, ESP, mean_sp, 0, NPF);
    AggJob aSW  = mkAgg(x_pfas, off_ps, poff_ps, NSW, EPS, mean_sw, 0, NSW);
    AggJob aGW0 = mkAgg(x_pfas, off_pg, poff_pg, NGW, EPG, mean_gw, gb[0], gb[1]);
    AggJob aGW1 = mkAgg(x_pfas, off_pg, poff_pg, NGW, EPG, mean_gw, gb[1], gb[2]);
    AggJob aGW2 = mkAgg(x_pfas, off_pg, poff_pg, NGW, EPG, mean_gw, gb[2], gb[3]);
    AggJob aGW3 = mkAgg(x_pfas, off_pg, poff_pg, NGW, EPG, mean_gw, gb[3], gb[4]);

    GemmJob gPF;
    gPF.A0 = mean_gp; gPF.A1 = mean_sp; gPF.A2 = x_pfas;
    gPF.W0 = Wl_gp; gPF.W1 = Wl_sp; gPF.W2 = wr_comb;
    gPF.bias1 = bl_gp; gPF.bias2 = bl_sp; gPF.whead = nullptr; gPF.bhead = nullptr;
    gPF.out = out_hpf; gPF.row_base = 0; gPF.n_rows = NPF;
    gPF.nseg = 3; gPF.mode = 0; gPF.nblocks = (NPF + 127) / 128;

    GemmJob gSW;
    gSW.A0 = mean_sw; gSW.A1 = x_sw; gSW.A2 = nullptr;
    gSW.W0 = Wl_ps; gSW.W1 = Wr_ps; gSW.W2 = nullptr;
    gSW.bias1 = bl_ps; gSW.bias2 = nullptr; gSW.whead = W_sw; gSW.bhead = b_sw;
    gSW.out = out_sw; gSW.row_base = 0; gSW.n_rows = NSW;
    gSW.nseg = 2; gSW.mode = 1; gSW.nblocks = (NSW + 127) / 128;

    GemmJob gGWa;  // rows [0, 76800)
    gGWa.A0 = mean_gw; gGWa.A1 = x_gw; gGWa.A2 = nullptr;
    gGWa.W0 = Wl_pg; gGWa.W1 = Wr_pg; gGWa.W2 = nullptr;
    gGWa.bias1 = bl_pg; gGWa.bias2 = nullptr; gGWa.whead = W_gw; gGWa.bhead = b_gw;
    gGWa.out = out_gw; gGWa.row_base = 0; gGWa.n_rows = gb[3];
    gGWa.nseg = 2; gGWa.mode = 1; gGWa.nblocks = gb[3] / 128;  // 600

    GemmJob gGWb;  // rows [76800, 100000)
    gGWb = gGWa;
    gGWb.row_base = gb[3]; gGWb.n_rows = NGW;
    gGWb.nblocks = (NGW - gb[3] + 127) / 128;                  // 182

    // P1: pure aggregation (gp + sp + sw)
    {
        int nb = aGP.nblocks + aSP.nblocks + aSW.nblocks;
        mega_kernel<<<nb, 256>>>(GZ, GZ, aGP, aSP, aSW);
    }
    // P2: gemm pf + sw  ||  agg gw slices 0-2
    {
        int nb = gPF.nblocks + gSW.nblocks + aGW0.nblocks + aGW1.nblocks + aGW2.nblocks;
        mega_kernel<<<nb, 256>>>(gPF, gSW, aGW0, aGW1, aGW2);
    }
    // P3: gemm gw rows[0,76800)  ||  agg gw slice 3
    {
        int nb = gGWa.nblocks + aGW3.nblocks;
        mega_kernel<<<nb, 256>>>(gGWa, GZ, aGW3, AZ, AZ);
    }
    // P4: gemm gw tail
    {
        mega_kernel<<<gGWb.nblocks, 256>>>(gGWb, GZ, AZ, AZ, AZ);
    }

    (void)n_in; (void)out_size; (void)in_sizes;
}